// round 16
// baseline (speedup 1.0000x reference)
// bf16-split mma.sync + fused proj chains + fused softmax-stats attention.
#include <cuda_runtime.h>
#include <cuda_bf16.h>
#include <cstdint>
#include <math.h>

#define HDIM 256
typedef __nv_bfloat16 bf16;

// ---------------- scratch (device globals) ----------------
__device__ float g_q [16*1024*256];
__device__ float g_k [16*2048*256];
__device__ float g_v [16*2048*256];
__device__ float g_vt[16*2048*256];
__device__ float g_s [16LL*1024*2048];
__device__ float g_at[16*1024*256];
__device__ float g_xA[16*1024*256];
__device__ float g_xB[16*1024*256];
__device__ float g_wqT[12*65536];
__device__ float g_wkT[12*65536];
__device__ float g_wvT[12*65536];
__device__ float2 g_stats[16*1024*16];   // per-(row, n-tile) partial (max, sum)
__device__ float2 g_rs[16*1024];         // per-row (max, 1/l)
__device__ int g_mt_hf, g_mt_fg;

// ---------------- helpers ----------------
__device__ __forceinline__ uint32_t smem_u32(const void* p){
    uint32_t a; asm("{ .reg .u64 t; cvta.to.shared.u64 t, %1; cvt.u32.u64 %0, t; }":"=r"(a):"l"(p)); return a;
}
__device__ __forceinline__ void ldsm4(uint32_t addr, uint32_t* r){
    asm volatile("ldmatrix.sync.aligned.m8n8.x4.shared.b16 {%0,%1,%2,%3}, [%4];"
        : "=r"(r[0]),"=r"(r[1]),"=r"(r[2]),"=r"(r[3]) : "r"(addr));
}
__device__ __forceinline__ void mma16816(float* c, const uint32_t* a, const uint32_t* b){
    asm volatile("mma.sync.aligned.m16n8k16.row.col.f32.bf16.bf16.f32 "
        "{%0,%1,%2,%3},{%4,%5,%6,%7},{%8,%9},{%0,%1,%2,%3};"
        : "+f"(c[0]),"+f"(c[1]),"+f"(c[2]),"+f"(c[3])
        : "r"(a[0]),"r"(a[1]),"r"(a[2]),"r"(a[3]),"r"(b[0]),"r"(b[1]));
}
__device__ __forceinline__ void split4(float4 v, uint2& h, uint2& l){
    bf16 hb[4], lb[4];
    float xs[4] = {v.x, v.y, v.z, v.w};
    #pragma unroll
    for (int i=0;i<4;i++){ hb[i]=__float2bfloat16(xs[i]); lb[i]=__float2bfloat16(xs[i]-__bfloat162float(hb[i])); }
    h = *(uint2*)hb; l = *(uint2*)lb;
}
__device__ __forceinline__ bool mchk(const void* m, int mt, long long idx){
    if (mt==0) return ((const int*)m)[idx]!=0;
    if (mt==1) return ((const uint8_t*)m)[idx]!=0;
    return ((const float*)m)[idx]!=0.f;
}

// ============================================================================
// Fused 3-stage projection (unchanged from R8).
// ============================================================================
#define ASST 264
#define BSST 72
#define PSMEM ((2*128*ASST + 2*256*BSST)*2)

__global__ __launch_bounds__(512, 1)
void proj_fused(const float* __restrict__ X, const float* __restrict__ WT,
                const float* __restrict__ bias, float* __restrict__ Out)
{
    extern __shared__ bf16 sm[];
    bf16* sAh = sm;
    bf16* sAl = sm + 128*ASST;
    bf16* sBh = sm + 2*128*ASST;
    bf16* sBl = sm + 2*128*ASST + 256*BSST;

    const int tid = threadIdx.x, warp = tid>>5, lane = tid&31;
    const int wm = warp>>2, wn = warp&3;
    const long long m0 = (long long)blockIdx.x * 128;

    const uint32_t bAh = smem_u32(sAh), bAl = smem_u32(sAl);
    const uint32_t bBh = smem_u32(sBh), bBl = smem_u32(sBl);

    #pragma unroll
    for (int i=0;i<16;i++){
        int id = tid + (i<<9);
        int r = id>>6, c4 = (id&63)<<2;
        uint2 h, l;
        split4(*(const float4*)(X + (m0+r)*256 + c4), h, l);
        *(uint2*)(sAh + r*ASST + c4) = h;
        *(uint2*)(sAl + r*ASST + c4) = l;
    }

    float acc[2][8][4];

    #pragma unroll 1
    for (int s=0; s<3; s++){
        const float* W  = WT + s*65536;
        const float* bp = bias + s*256;
        #pragma unroll
        for (int mi=0;mi<2;mi++)
            #pragma unroll
            for (int ni=0;ni<8;ni++)
                #pragma unroll
                for (int t=0;t<4;t++) acc[mi][ni][t] = 0.f;

        #pragma unroll 1
        for (int kc=0; kc<4; kc++){
            const int k0 = kc<<6;
            #pragma unroll
            for (int i=0;i<8;i++){
                int id = tid + (i<<9);
                int r = id>>4, c4 = (id&15)<<2;
                uint2 h, l;
                split4(*(const float4*)(W + r*256 + k0 + c4), h, l);
                *(uint2*)(sBh + r*BSST + c4) = h;
                *(uint2*)(sBl + r*BSST + c4) = l;
            }
            __syncthreads();

            #pragma unroll
            for (int k16=0; k16<4; k16++){
                const uint32_t acol = (k0 + k16*16)*2 + ((lane>>4)<<4);
                const uint32_t arow = (wm*32 + (lane&15)) * (ASST*2);
                uint32_t Ah[2][4], Al[2][4];
                #pragma unroll
                for (int mi=0;mi<2;mi++){
                    ldsm4(bAh + arow + mi*16*(ASST*2) + acol, Ah[mi]);
                    ldsm4(bAl + arow + mi*16*(ASST*2) + acol, Al[mi]);
                }
                const uint32_t bcol = k16*32 + (((lane>>3)&1)<<4);
                #pragma unroll
                for (int bi=0;bi<4;bi++){
                    const uint32_t brow = (wn*64 + bi*16 + ((lane>>4)<<3) + (lane&7)) * (BSST*2);
                    uint32_t Bh[4], Bl[4];
                    ldsm4(bBh + brow + bcol, Bh);
                    ldsm4(bBl + brow + bcol, Bl);
                    #pragma unroll
                    for (int mi=0;mi<2;mi++)
                        #pragma unroll
                        for (int nh=0;nh<2;nh++){
                            int ni = bi*2+nh;
                            mma16816(acc[mi][ni], Ah[mi], &Bh[nh*2]);
                            mma16816(acc[mi][ni], Ah[mi], &Bl[nh*2]);
                            mma16816(acc[mi][ni], Al[mi], &Bh[nh*2]);
                        }
                }
            }
            __syncthreads();
        }

        const int rbase = wm*32 + (lane>>2);
        const int cbase = wn*64 + (lane&3)*2;
        if (s < 2){
            #pragma unroll
            for (int mi=0;mi<2;mi++)
                #pragma unroll
                for (int ni=0;ni<8;ni++)
                    #pragma unroll
                    for (int half=0; half<2; half++){
                        int r = rbase + mi*16 + half*8;
                        int c = cbase + ni*8;
                        float v0 = acc[mi][ni][half*2+0] + __ldg(bp+c);
                        float v1 = acc[mi][ni][half*2+1] + __ldg(bp+c+1);
                        bf16 h0 = __float2bfloat16(v0);
                        bf16 h1 = __float2bfloat16(v1);
                        sAh[r*ASST+c]   = h0;
                        sAh[r*ASST+c+1] = h1;
                        sAl[r*ASST+c]   = __float2bfloat16(v0 - __bfloat162float(h0));
                        sAl[r*ASST+c+1] = __float2bfloat16(v1 - __bfloat162float(h1));
                    }
            __syncthreads();
        } else {
            #pragma unroll
            for (int mi=0;mi<2;mi++)
                #pragma unroll
                for (int ni=0;ni<8;ni++)
                    #pragma unroll
                    for (int half=0; half<2; half++){
                        int r = rbase + mi*16 + half*8;
                        int c = cbase + ni*8;
                        float2 v;
                        v.x = acc[mi][ni][half*2+0] + __ldg(bp+c);
                        v.y = acc[mi][ni][half*2+1] + __ldg(bp+c+1);
                        *(float2*)(Out + (m0+r)*256 + c) = v;
                    }
        }
    }
}

// ============================================================================
// Attention GEMMs. MODE 0 (QK): C = masked(alpha*A@B^T), epilogue emits
// per-(row,tile) softmax partials (max, sum) to stats. MODE 1 (SV): A values
// transformed a = exp(s - m)*invl on load (softmax applied in-GEMM).
// CTA 128x128, K-chunk 64, 512 thr, register prefetch (same core as R7/R8).
// ============================================================================
#define SST 72
#define GSMEM (4*128*SST*2)

template<int MODE>
__global__ __launch_bounds__(512)
void gemm_attn(const float* __restrict__ A, const float* __restrict__ B,
               float* __restrict__ C, int N, int K,
               long long szA, long long szB, long long szC, float alpha,
               const void* __restrict__ mask, const int* __restrict__ mtp,
               float2* __restrict__ stats, const float2* __restrict__ rs)
{
    extern __shared__ bf16 smem[];
    bf16* sAh = smem;
    bf16* sAl = smem + 128*SST;
    bf16* sBh = smem + 2*128*SST;
    bf16* sBl = smem + 3*128*SST;

    const int tid = threadIdx.x, warp = tid>>5, lane = tid&31;
    const int wm = warp>>2, wn = warp&3;
    const int m0 = blockIdx.y*128, n0 = blockIdx.x*128, z = blockIdx.z;
    A += (long long)z*szA; B += (long long)z*szB;

    const uint32_t bAh = smem_u32(sAh), bAl = smem_u32(sAl);
    const uint32_t bBh = smem_u32(sBh), bBl = smem_u32(sBl);

    float acc[2][4][4];
    #pragma unroll
    for (int i=0;i<2;i++)
        #pragma unroll
        for (int j=0;j<4;j++)
            #pragma unroll
            for (int t=0;t<4;t++) acc[i][j][t] = 0.f;

    int fr[4], fc[4];
    #pragma unroll
    for (int i=0;i<4;i++){ int id = tid + (i<<9); fr[i]=id>>4; fc[i]=(id&15)<<2; }

    float2 rsv[4];
    if (MODE==1){
        #pragma unroll
        for (int i=0;i<4;i++) rsv[i] = __ldg(&rs[(long long)z*1024 + m0 + fr[i]]);
    }

    float4 pA[4], pB[4];
    #pragma unroll
    for (int i=0;i<4;i++){
        pA[i] = *(const float4*)(A + (long long)(m0+fr[i])*K + fc[i]);
        pB[i] = *(const float4*)(B + (long long)(n0+fr[i])*K + fc[i]);
    }

    const int nch = K >> 6;
    for (int kc=0; kc<nch; kc++){
        #pragma unroll
        for (int i=0;i<4;i++){
            float4 ra = pA[i];
            if (MODE==1){
                ra.x = __expf(ra.x - rsv[i].x)*rsv[i].y;
                ra.y = __expf(ra.y - rsv[i].x)*rsv[i].y;
                ra.z = __expf(ra.z - rsv[i].x)*rsv[i].y;
                ra.w = __expf(ra.w - rsv[i].x)*rsv[i].y;
            }
            uint2 h, l;
            split4(ra, h, l);
            *(uint2*)(sAh + fr[i]*SST + fc[i]) = h;
            *(uint2*)(sAl + fr[i]*SST + fc[i]) = l;
            split4(pB[i], h, l);
            *(uint2*)(sBh + fr[i]*SST + fc[i]) = h;
            *(uint2*)(sBl + fr[i]*SST + fc[i]) = l;
        }
        __syncthreads();

        if (kc+1 < nch){
            const int k0 = (kc+1)<<6;
            #pragma unroll
            for (int i=0;i<4;i++){
                pA[i] = *(const float4*)(A + (long long)(m0+fr[i])*K + k0 + fc[i]);
                pB[i] = *(const float4*)(B + (long long)(n0+fr[i])*K + k0 + fc[i]);
            }
        }

        #pragma unroll
        for (int k16=0; k16<4; k16++){
            const uint32_t akoff = k16*32 + ((lane>>4)<<4);
            const uint32_t bkoff = k16*32 + (((lane>>3)&1)<<4);
            const uint32_t arow  = (wm*32 + (lane&15)) * (SST*2);
            const uint32_t brow  = (wn*32 + ((lane>>4)<<3) + (lane&7)) * (SST*2);

            uint32_t Ah[2][4], Al[2][4], Bh[2][4], Bl[2][4];
            #pragma unroll
            for (int mi=0;mi<2;mi++){
                ldsm4(bAh + arow + mi*16*(SST*2) + akoff, Ah[mi]);
                ldsm4(bAl + arow + mi*16*(SST*2) + akoff, Al[mi]);
            }
            #pragma unroll
            for (int bi=0;bi<2;bi++){
                ldsm4(bBh + brow + bi*16*(SST*2) + bkoff, Bh[bi]);
                ldsm4(bBl + brow + bi*16*(SST*2) + bkoff, Bl[bi]);
            }
            #pragma unroll
            for (int mi=0;mi<2;mi++)
                #pragma unroll
                for (int ni=0;ni<4;ni++){
                    mma16816(acc[mi][ni], Ah[mi], &Bh[ni>>1][(ni&1)*2]);
                    mma16816(acc[mi][ni], Ah[mi], &Bl[ni>>1][(ni&1)*2]);
                    mma16816(acc[mi][ni], Al[mi], &Bh[ni>>1][(ni&1)*2]);
                }
        }
        __syncthreads();
    }

    C += (long long)z*szC;

    if (MODE==0){
        // masked scaled scores + per-(row, tile) softmax partials
        float* smr = (float*)smem;   // [128][8]: [r*8+wn]=max, [r*8+4+wn]=sum
        const int mt = *mtp;
        const long long mbase = (long long)z * 1024LL * N;
        #pragma unroll
        for (int mi=0;mi<2;mi++)
            #pragma unroll
            for (int half=0; half<2; half++){
                int rl = wm*32 + mi*16 + (lane>>2) + half*8;
                long long row = m0 + rl;
                float vals[8]; float rm = -1e30f;
                #pragma unroll
                for (int ni=0;ni<4;ni++)
                    #pragma unroll
                    for (int e=0;e<2;e++){
                        int c = n0 + wn*32 + ni*8 + (lane&3)*2 + e;
                        float v = acc[mi][ni][half*2+e]*alpha;
                        if (mchk(mask, mt, mbase + row*(long long)N + c)) v = -1e30f;
                        vals[ni*2+e] = v;
                        rm = fmaxf(rm, v);
                    }
                float rsum = 0.f;
                #pragma unroll
                for (int j=0;j<8;j++) rsum += __expf(vals[j]-rm);
                #pragma unroll
                for (int ni=0;ni<4;ni++)
                    *(float2*)(C + row*(long long)N + n0 + wn*32 + ni*8 + (lane&3)*2)
                        = make_float2(vals[ni*2], vals[ni*2+1]);
                #pragma unroll
                for (int d=1; d<4; d<<=1){
                    float om = __shfl_xor_sync(0xffffffffu, rm, d);
                    float os = __shfl_xor_sync(0xffffffffu, rsum, d);
                    float nm = fmaxf(rm, om);
                    rsum = rsum*__expf(rm-nm) + os*__expf(om-nm);
                    rm = nm;
                }
                if ((lane&3)==0){ smr[rl*8+wn] = rm; smr[rl*8+4+wn] = rsum; }
            }
        __syncthreads();
        if (tid < 128){
            float m = -1e30f;
            #pragma unroll
            for (int w=0;w<4;w++) m = fmaxf(m, smr[tid*8+w]);
            float ssum = 0.f;
            #pragma unroll
            for (int w=0;w<4;w++) ssum += smr[tid*8+4+w]*__expf(smr[tid*8+w]-m);
            stats[((long long)z*1024 + m0 + tid)*16 + blockIdx.x] = make_float2(m, ssum);
        }
    } else {
        const int mrow = m0 + wm*32 + (lane>>2);
        const int ncol = n0 + wn*32 + (lane&3)*2;
        #pragma unroll
        for (int mi=0;mi<2;mi++)
            #pragma unroll
            for (int ni=0;ni<4;ni++)
                #pragma unroll
                for (int half=0; half<2; half++){
                    int r = mrow + mi*16 + half*8;
                    int c = ncol + ni*8;
                    float2 v;
                    v.x = acc[mi][ni][half*2+0]*alpha;
                    v.y = acc[mi][ni][half*2+1]*alpha;
                    *(float2*)(C + (long long)r*N + c) = v;
                }
    }
}

// ---------------- merge per-tile stats -> per-row (max, 1/l) ----------------
__global__ void merge_stats(const float2* __restrict__ stats,
                            float2* __restrict__ rs, int T)
{
    int r = blockIdx.x*256 + threadIdx.x;   // 16384 rows
    const float2* p = stats + (long long)r*16;
    float m = -1e30f;
    for (int t=0;t<T;t++) m = fmaxf(m, p[t].x);
    float l = 0.f;
    for (int t=0;t<T;t++) l += p[t].y*__expf(p[t].x - m);
    float inv = (m <= -1e29f || l <= 0.f) ? 0.f : 1.f/l;
    rs[r] = make_float2(m, inv);
}

// ---------------- transpose: out[z][c][r] = in[z][r][c] ----------------
__global__ void transpose_k(const float* __restrict__ in, float* __restrict__ out,
                            int R, int C, long long sIn, long long sOut)
{
    __shared__ float t[32][33];
    const int z = blockIdx.z;
    in += (long long)z*sIn; out += (long long)z*sOut;
    int r0 = blockIdx.y*32, c0 = blockIdx.x*32;
    #pragma unroll
    for (int j=0;j<4;j++)
        t[threadIdx.y+j*8][threadIdx.x] = in[(long long)(r0+threadIdx.y+j*8)*C + c0+threadIdx.x];
    __syncthreads();
    #pragma unroll
    for (int j=0;j<4;j++)
        out[(long long)(c0+threadIdx.y+j*8)*R + r0+threadIdx.x] = t[threadIdx.x][threadIdx.y+j*8];
}

// ---------------- mask dtype detection (0=int32,1=uint8,2=float32) ----------
__global__ void detect_mask_kernel(const uint32_t* __restrict__ m, int nw, int* __restrict__ f)
{
    __shared__ int wg, bb;
    if (threadIdx.x==0){ wg=0; bb=0; }
    __syncthreads();
    int lw=0, lb=0;
    for (int i=threadIdx.x;i<nw;i+=blockDim.x){
        uint32_t w = m[i];
        if (w>1u) lw=1;
        #pragma unroll
        for (int b=0;b<4;b++) if (((w>>(8*b))&0xFFu)>1u) lb=1;
    }
    if (lw) atomicOr(&wg,1);
    if (lb) atomicOr(&bb,1);
    __syncthreads();
    if (threadIdx.x==0) *f = (!wg)?0:((!bb)?1:2);
}

// ---------------- LN + residual / final add ----------------
__device__ __forceinline__ float blk_red(float v){
    __shared__ float sh[256];
    int t = threadIdx.x; sh[t]=v; __syncthreads();
    #pragma unroll
    for (int s=128;s>0;s>>=1){ if (t<s) sh[t]=sh[t]+sh[t+s]; __syncthreads(); }
    float r = sh[0]; __syncthreads(); return r;
}

__global__ __launch_bounds__(256)
void ln_res_kernel(const float* __restrict__ x, const float* __restrict__ res,
                   const float* __restrict__ gm, const float* __restrict__ bt,
                   float* __restrict__ out)
{
    const long long row = blockIdx.x;
    const int t = threadIdx.x;
    float v = x[row*HDIM+t];
    float mu = blk_red(v)*(1.f/HDIM);
    float d = v-mu;
    float var = blk_red(d*d)*(1.f/HDIM);
    out[row*HDIM+t] = d*rsqrtf(var+1e-5f)*gm[t]+bt[t] + res[row*HDIM+t];
}

__global__ void add_kernel(const float* __restrict__ a, const float* __restrict__ b,
                           float* __restrict__ o, long long n)
{
    long long i = (long long)blockIdx.x*blockDim.x + threadIdx.x;
    if (i<n) o[i] = a[i]+b[i];
}

// ---------------- host orchestration ----------------
static void run_layer(const float* x1, const float* x2, const void* mask,
                      const int* mt, int Nk,
                      const float* wqT, const float* bq_l,
                      const float* wkT, const float* bk_l,
                      const float* wvT, const float* bv_l,
                      const float* gm, const float* bt, float* xout,
                      float* q, float* k, float* v, float* vt, float* s,
                      float* at, float2* stats, float2* rsb)
{
    const int Bb=16, Nq=1024;
    proj_fused<<<Bb*Nq/128, 512, PSMEM>>>(x1, wqT, bq_l, q);
    proj_fused<<<Bb*Nk/128, 512, PSMEM>>>(x2, wkT, bk_l, k);
    proj_fused<<<Bb*Nk/128, 512, PSMEM>>>(x2, wvT, bv_l, v);
    {
        dim3 g(HDIM/32, Nk/32, Bb);
        transpose_k<<<g, dim3(32,8)>>>(v, vt, Nk, HDIM, (long long)Nk*HDIM, (long long)Nk*HDIM);
    }
    // QK: masked scaled scores + softmax partials
    {
        dim3 g(Nk/128, Nq/128, Bb);
        gemm_attn<0><<<g, 512, GSMEM>>>(q, k, s, Nk, HDIM,
            (long long)Nq*HDIM, (long long)Nk*HDIM, (long long)Nq*Nk, 0.0625f,
            mask, mt, stats, nullptr);
    }
    merge_stats<<<64, 256>>>(stats, rsb, Nk/128);
    // SV: softmax applied on A load
    {
        dim3 g(HDIM/128, Nq/128, Bb);
        gemm_attn<1><<<g, 512, GSMEM>>>(s, vt, at, HDIM, Nk,
            (long long)Nq*Nk, (long long)Nk*HDIM, (long long)Nq*HDIM, 1.f,
            nullptr, nullptr, nullptr, rsb);
    }
    ln_res_kernel<<<Bb*Nq, 256>>>(at, x1, gm, bt, xout);
}

extern "C" void kernel_launch(void* const* d_in, const int* in_sizes, int n_in,
                              void* d_out, int out_size)
{
    const float* future  = (const float*)d_in[0];
    const float* history = (const float*)d_in[1];
    const float* graph   = (const float*)d_in[2];
    const void*  mask_hf = d_in[3];
    const void*  mask_fg = d_in[4];
    const float* Wq = (const float*)d_in[5];
    const float* bq = (const float*)d_in[6];
    const float* Wk = (const float*)d_in[7];
    const float* bk = (const float*)d_in[8];
    const float* Wv = (const float*)d_in[9];
    const float* bv = (const float*)d_in[10];
    const float* gm = (const float*)d_in[11];
    const float* bt = (const float*)d_in[12];
    float* out = (float*)d_out;

    cudaFuncSetAttribute(gemm_attn<0>, cudaFuncAttributeMaxDynamicSharedMemorySize, GSMEM);
    cudaFuncSetAttribute(gemm_attn<1>, cudaFuncAttributeMaxDynamicSharedMemorySize, GSMEM);
    cudaFuncSetAttribute(proj_fused,   cudaFuncAttributeMaxDynamicSharedMemorySize, PSMEM);

    float *q,*k,*v,*vt,*s,*at,*xA,*xB,*wqT,*wkT,*wvT;
    float2 *stats,*rsb;
    int *mhf,*mfg;
    cudaGetSymbolAddress((void**)&q,g_q);     cudaGetSymbolAddress((void**)&k,g_k);
    cudaGetSymbolAddress((void**)&v,g_v);     cudaGetSymbolAddress((void**)&vt,g_vt);
    cudaGetSymbolAddress((void**)&s,g_s);     cudaGetSymbolAddress((void**)&at,g_at);
    cudaGetSymbolAddress((void**)&xA,g_xA);   cudaGetSymbolAddress((void**)&xB,g_xB);
    cudaGetSymbolAddress((void**)&wqT,g_wqT); cudaGetSymbolAddress((void**)&wkT,g_wkT);
    cudaGetSymbolAddress((void**)&wvT,g_wvT);
    cudaGetSymbolAddress((void**)&stats,g_stats);
    cudaGetSymbolAddress((void**)&rsb,g_rs);
    cudaGetSymbolAddress((void**)&mhf,g_mt_hf); cudaGetSymbolAddress((void**)&mfg,g_mt_fg);

    {
        int nh = in_sizes[3]/4; if (nh>65536) nh=65536;
        int ng = in_sizes[4]/4; if (ng>65536) ng=65536;
        detect_mask_kernel<<<1,256>>>((const uint32_t*)mask_hf, nh, mhf);
        detect_mask_kernel<<<1,256>>>((const uint32_t*)mask_fg, ng, mfg);
    }
    {
        dim3 g(8,8,12), b(32,8);
        transpose_k<<<g,b>>>(Wq, wqT, 256,256, 65536,65536);
        transpose_k<<<g,b>>>(Wk, wkT, 256,256, 65536,65536);
        transpose_k<<<g,b>>>(Wv, wvT, 256,256, 65536,65536);
    }

    const long long WL = 3LL*65536, BL = 3LL*256;
    run_layer(future, history, mask_hf, mhf, 1024,
              wqT+0*WL, bq+0*BL, wkT+0*WL, bk+0*BL, wvT+0*WL, bv+0*BL,
              gm+0*256, bt+0*256, xA, q,k,v,vt,s,at,stats,rsb);
    run_layer(xA, history, mask_hf, mhf, 1024,
              wqT+1*WL, bq+1*BL, wkT+1*WL, bk+1*BL, wvT+1*WL, bv+1*BL,
              gm+1*256, bt+1*256, xB, q,k,v,vt,s,at,stats,rsb);
    run_layer(xB, graph, mask_fg, mfg, 2048,
              wqT+2*WL, bq+2*BL, wkT+2*WL, bk+2*BL, wvT+2*WL, bv+2*BL,
              gm+2*256, bt+2*256, xA, q,k,v,vt,s,at,stats,rsb);
    run_layer(xA, graph, mask_fg, mfg, 2048,
              wqT+3*WL, bq+3*BL, wkT+3*WL, bk+3*BL, wvT+3*WL, bv+3*BL,
              gm+3*256, bt+3*256, xB, q,k,v,vt,s,at,stats,rsb);

    long long n = (long long)out_size;
    add_kernel<<<(unsigned)((n+255)/256),256>>>(future, xB, out, n);
}

// round 17
// speedup vs baseline: 1.0043x; 1.0043x over previous
// bf16-split mma.sync + fused proj chains + fused softmax-stats attention.
#include <cuda_runtime.h>
#include <cuda_bf16.h>
#include <cstdint>
#include <math.h>

#define HDIM 256
typedef __nv_bfloat16 bf16;

// ---------------- scratch (device globals) ----------------
__device__ float g_q [16*1024*256];
__device__ float g_k [16*2048*256];
__device__ float g_v [16*2048*256];
__device__ float g_vt[16*2048*256];
__device__ float g_s [16LL*1024*2048];
__device__ float g_at[16*1024*256];
__device__ float g_xA[16*1024*256];
__device__ float g_xB[16*1024*256];
__device__ float g_wqT[12*65536];
__device__ float g_wkT[12*65536];
__device__ float g_wvT[12*65536];
__device__ float2 g_stats[16*1024*16];   // per-(row, n-tile) partial (max, sum)
__device__ float2 g_rs[16*1024];         // per-row (max, 1/l)
__device__ int g_mt_hf, g_mt_fg;

// ---------------- helpers ----------------
__device__ __forceinline__ uint32_t smem_u32(const void* p){
    uint32_t a; asm("{ .reg .u64 t; cvta.to.shared.u64 t, %1; cvt.u32.u64 %0, t; }":"=r"(a):"l"(p)); return a;
}
__device__ __forceinline__ void ldsm4(uint32_t addr, uint32_t* r){
    asm volatile("ldmatrix.sync.aligned.m8n8.x4.shared.b16 {%0,%1,%2,%3}, [%4];"
        : "=r"(r[0]),"=r"(r[1]),"=r"(r[2]),"=r"(r[3]) : "r"(addr));
}
__device__ __forceinline__ void mma16816(float* c, const uint32_t* a, const uint32_t* b){
    asm volatile("mma.sync.aligned.m16n8k16.row.col.f32.bf16.bf16.f32 "
        "{%0,%1,%2,%3},{%4,%5,%6,%7},{%8,%9},{%0,%1,%2,%3};"
        : "+f"(c[0]),"+f"(c[1]),"+f"(c[2]),"+f"(c[3])
        : "r"(a[0]),"r"(a[1]),"r"(a[2]),"r"(a[3]),"r"(b[0]),"r"(b[1]));
}
__device__ __forceinline__ void split4(float4 v, uint2& h, uint2& l){
    bf16 hb[4], lb[4];
    float xs[4] = {v.x, v.y, v.z, v.w};
    #pragma unroll
    for (int i=0;i<4;i++){ hb[i]=__float2bfloat16(xs[i]); lb[i]=__float2bfloat16(xs[i]-__bfloat162float(hb[i])); }
    h = *(uint2*)hb; l = *(uint2*)lb;
}
__device__ __forceinline__ bool mchk(const void* m, int mt, long long idx){
    if (mt==0) return ((const int*)m)[idx]!=0;
    if (mt==1) return ((const uint8_t*)m)[idx]!=0;
    return ((const float*)m)[idx]!=0.f;
}

// ============================================================================
// Fused 3-stage projection (unchanged from R8).
// ============================================================================
#define ASST 264
#define BSST 72
#define PSMEM ((2*128*ASST + 2*256*BSST)*2)

__global__ __launch_bounds__(512, 1)
void proj_fused(const float* __restrict__ X, const float* __restrict__ WT,
                const float* __restrict__ bias, float* __restrict__ Out)
{
    extern __shared__ bf16 sm[];
    bf16* sAh = sm;
    bf16* sAl = sm + 128*ASST;
    bf16* sBh = sm + 2*128*ASST;
    bf16* sBl = sm + 2*128*ASST + 256*BSST;

    const int tid = threadIdx.x, warp = tid>>5, lane = tid&31;
    const int wm = warp>>2, wn = warp&3;
    const long long m0 = (long long)blockIdx.x * 128;

    const uint32_t bAh = smem_u32(sAh), bAl = smem_u32(sAl);
    const uint32_t bBh = smem_u32(sBh), bBl = smem_u32(sBl);

    #pragma unroll
    for (int i=0;i<16;i++){
        int id = tid + (i<<9);
        int r = id>>6, c4 = (id&63)<<2;
        uint2 h, l;
        split4(*(const float4*)(X + (m0+r)*256 + c4), h, l);
        *(uint2*)(sAh + r*ASST + c4) = h;
        *(uint2*)(sAl + r*ASST + c4) = l;
    }

    float acc[2][8][4];

    #pragma unroll 1
    for (int s=0; s<3; s++){
        const float* W  = WT + s*65536;
        const float* bp = bias + s*256;
        #pragma unroll
        for (int mi=0;mi<2;mi++)
            #pragma unroll
            for (int ni=0;ni<8;ni++)
                #pragma unroll
                for (int t=0;t<4;t++) acc[mi][ni][t] = 0.f;

        #pragma unroll 1
        for (int kc=0; kc<4; kc++){
            const int k0 = kc<<6;
            #pragma unroll
            for (int i=0;i<8;i++){
                int id = tid + (i<<9);
                int r = id>>4, c4 = (id&15)<<2;
                uint2 h, l;
                split4(*(const float4*)(W + r*256 + k0 + c4), h, l);
                *(uint2*)(sBh + r*BSST + c4) = h;
                *(uint2*)(sBl + r*BSST + c4) = l;
            }
            __syncthreads();

            #pragma unroll
            for (int k16=0; k16<4; k16++){
                const uint32_t acol = (k0 + k16*16)*2 + ((lane>>4)<<4);
                const uint32_t arow = (wm*32 + (lane&15)) * (ASST*2);
                uint32_t Ah[2][4], Al[2][4];
                #pragma unroll
                for (int mi=0;mi<2;mi++){
                    ldsm4(bAh + arow + mi*16*(ASST*2) + acol, Ah[mi]);
                    ldsm4(bAl + arow + mi*16*(ASST*2) + acol, Al[mi]);
                }
                const uint32_t bcol = k16*32 + (((lane>>3)&1)<<4);
                #pragma unroll
                for (int bi=0;bi<4;bi++){
                    const uint32_t brow = (wn*64 + bi*16 + ((lane>>4)<<3) + (lane&7)) * (BSST*2);
                    uint32_t Bh[4], Bl[4];
                    ldsm4(bBh + brow + bcol, Bh);
                    ldsm4(bBl + brow + bcol, Bl);
                    #pragma unroll
                    for (int mi=0;mi<2;mi++)
                        #pragma unroll
                        for (int nh=0;nh<2;nh++){
                            int ni = bi*2+nh;
                            mma16816(acc[mi][ni], Ah[mi], &Bh[nh*2]);
                            mma16816(acc[mi][ni], Ah[mi], &Bl[nh*2]);
                            mma16816(acc[mi][ni], Al[mi], &Bh[nh*2]);
                        }
                }
            }
            __syncthreads();
        }

        const int rbase = wm*32 + (lane>>2);
        const int cbase = wn*64 + (lane&3)*2;
        if (s < 2){
            #pragma unroll
            for (int mi=0;mi<2;mi++)
                #pragma unroll
                for (int ni=0;ni<8;ni++)
                    #pragma unroll
                    for (int half=0; half<2; half++){
                        int r = rbase + mi*16 + half*8;
                        int c = cbase + ni*8;
                        float v0 = acc[mi][ni][half*2+0] + __ldg(bp+c);
                        float v1 = acc[mi][ni][half*2+1] + __ldg(bp+c+1);
                        bf16 h0 = __float2bfloat16(v0);
                        bf16 h1 = __float2bfloat16(v1);
                        sAh[r*ASST+c]   = h0;
                        sAh[r*ASST+c+1] = h1;
                        sAl[r*ASST+c]   = __float2bfloat16(v0 - __bfloat162float(h0));
                        sAl[r*ASST+c+1] = __float2bfloat16(v1 - __bfloat162float(h1));
                    }
            __syncthreads();
        } else {
            #pragma unroll
            for (int mi=0;mi<2;mi++)
                #pragma unroll
                for (int ni=0;ni<8;ni++)
                    #pragma unroll
                    for (int half=0; half<2; half++){
                        int r = rbase + mi*16 + half*8;
                        int c = cbase + ni*8;
                        float2 v;
                        v.x = acc[mi][ni][half*2+0] + __ldg(bp+c);
                        v.y = acc[mi][ni][half*2+1] + __ldg(bp+c+1);
                        *(float2*)(Out + (m0+r)*256 + c) = v;
                    }
        }
    }
}

// ============================================================================
// Attention GEMMs. MODE 0 (QK): C = masked(alpha*A@B^T), epilogue emits
// per-(row,tile) softmax partials (max, sum) to stats. MODE 1 (SV): A values
// transformed a = exp(s - m)*invl on load (softmax applied in-GEMM).
// CTA 128x128, K-chunk 64, 512 thr, register prefetch (same core as R7/R8).
// ============================================================================
#define SST 72
#define GSMEM (4*128*SST*2)

template<int MODE>
__global__ __launch_bounds__(512)
void gemm_attn(const float* __restrict__ A, const float* __restrict__ B,
               float* __restrict__ C, int N, int K,
               long long szA, long long szB, long long szC, float alpha,
               const void* __restrict__ mask, const int* __restrict__ mtp,
               float2* __restrict__ stats, const float2* __restrict__ rs)
{
    extern __shared__ bf16 smem[];
    bf16* sAh = smem;
    bf16* sAl = smem + 128*SST;
    bf16* sBh = smem + 2*128*SST;
    bf16* sBl = smem + 3*128*SST;

    const int tid = threadIdx.x, warp = tid>>5, lane = tid&31;
    const int wm = warp>>2, wn = warp&3;
    const int m0 = blockIdx.y*128, n0 = blockIdx.x*128, z = blockIdx.z;
    A += (long long)z*szA; B += (long long)z*szB;

    const uint32_t bAh = smem_u32(sAh), bAl = smem_u32(sAl);
    const uint32_t bBh = smem_u32(sBh), bBl = smem_u32(sBl);

    float acc[2][4][4];
    #pragma unroll
    for (int i=0;i<2;i++)
        #pragma unroll
        for (int j=0;j<4;j++)
            #pragma unroll
            for (int t=0;t<4;t++) acc[i][j][t] = 0.f;

    int fr[4], fc[4];
    #pragma unroll
    for (int i=0;i<4;i++){ int id = tid + (i<<9); fr[i]=id>>4; fc[i]=(id&15)<<2; }

    float2 rsv[4];
    if (MODE==1){
        #pragma unroll
        for (int i=0;i<4;i++) rsv[i] = __ldg(&rs[(long long)z*1024 + m0 + fr[i]]);
    }

    float4 pA[4], pB[4];
    #pragma unroll
    for (int i=0;i<4;i++){
        pA[i] = *(const float4*)(A + (long long)(m0+fr[i])*K + fc[i]);
        pB[i] = *(const float4*)(B + (long long)(n0+fr[i])*K + fc[i]);
    }

    const int nch = K >> 6;
    for (int kc=0; kc<nch; kc++){
        #pragma unroll
        for (int i=0;i<4;i++){
            float4 ra = pA[i];
            if (MODE==1){
                ra.x = __expf(ra.x - rsv[i].x)*rsv[i].y;
                ra.y = __expf(ra.y - rsv[i].x)*rsv[i].y;
                ra.z = __expf(ra.z - rsv[i].x)*rsv[i].y;
                ra.w = __expf(ra.w - rsv[i].x)*rsv[i].y;
            }
            uint2 h, l;
            split4(ra, h, l);
            *(uint2*)(sAh + fr[i]*SST + fc[i]) = h;
            *(uint2*)(sAl + fr[i]*SST + fc[i]) = l;
            split4(pB[i], h, l);
            *(uint2*)(sBh + fr[i]*SST + fc[i]) = h;
            *(uint2*)(sBl + fr[i]*SST + fc[i]) = l;
        }
        __syncthreads();

        if (kc+1 < nch){
            const int k0 = (kc+1)<<6;
            #pragma unroll
            for (int i=0;i<4;i++){
                pA[i] = *(const float4*)(A + (long long)(m0+fr[i])*K + k0 + fc[i]);
                pB[i] = *(const float4*)(B + (long long)(n0+fr[i])*K + k0 + fc[i]);
            }
        }

        #pragma unroll
        for (int k16=0; k16<4; k16++){
            const uint32_t akoff = k16*32 + ((lane>>4)<<4);
            const uint32_t bkoff = k16*32 + (((lane>>3)&1)<<4);
            const uint32_t arow  = (wm*32 + (lane&15)) * (SST*2);
            const uint32_t brow  = (wn*32 + ((lane>>4)<<3) + (lane&7)) * (SST*2);

            uint32_t Ah[2][4], Al[2][4], Bh[2][4], Bl[2][4];
            #pragma unroll
            for (int mi=0;mi<2;mi++){
                ldsm4(bAh + arow + mi*16*(SST*2) + akoff, Ah[mi]);
                ldsm4(bAl + arow + mi*16*(SST*2) + akoff, Al[mi]);
            }
            #pragma unroll
            for (int bi=0;bi<2;bi++){
                ldsm4(bBh + brow + bi*16*(SST*2) + bkoff, Bh[bi]);
                ldsm4(bBl + brow + bi*16*(SST*2) + bkoff, Bl[bi]);
            }
            #pragma unroll
            for (int mi=0;mi<2;mi++)
                #pragma unroll
                for (int ni=0;ni<4;ni++){
                    mma16816(acc[mi][ni], Ah[mi], &Bh[ni>>1][(ni&1)*2]);
                    mma16816(acc[mi][ni], Ah[mi], &Bl[ni>>1][(ni&1)*2]);
                    mma16816(acc[mi][ni], Al[mi], &Bh[ni>>1][(ni&1)*2]);
                }
        }
        __syncthreads();
    }

    C += (long long)z*szC;

    if (MODE==0){
        // masked scaled scores + per-(row, tile) softmax partials
        float* smr = (float*)smem;   // [128][8]: [r*8+wn]=max, [r*8+4+wn]=sum
        const int mt = *mtp;
        const long long mbase = (long long)z * 1024LL * N;
        #pragma unroll
        for (int mi=0;mi<2;mi++)
            #pragma unroll
            for (int half=0; half<2; half++){
                int rl = wm*32 + mi*16 + (lane>>2) + half*8;
                long long row = m0 + rl;
                float vals[8]; float rm = -1e30f;
                #pragma unroll
                for (int ni=0;ni<4;ni++)
                    #pragma unroll
                    for (int e=0;e<2;e++){
                        int c = n0 + wn*32 + ni*8 + (lane&3)*2 + e;
                        float v = acc[mi][ni][half*2+e]*alpha;
                        if (mchk(mask, mt, mbase + row*(long long)N + c)) v = -1e30f;
                        vals[ni*2+e] = v;
                        rm = fmaxf(rm, v);
                    }
                float rsum = 0.f;
                #pragma unroll
                for (int j=0;j<8;j++) rsum += __expf(vals[j]-rm);
                #pragma unroll
                for (int ni=0;ni<4;ni++)
                    *(float2*)(C + row*(long long)N + n0 + wn*32 + ni*8 + (lane&3)*2)
                        = make_float2(vals[ni*2], vals[ni*2+1]);
                #pragma unroll
                for (int d=1; d<4; d<<=1){
                    float om = __shfl_xor_sync(0xffffffffu, rm, d);
                    float os = __shfl_xor_sync(0xffffffffu, rsum, d);
                    float nm = fmaxf(rm, om);
                    rsum = rsum*__expf(rm-nm) + os*__expf(om-nm);
                    rm = nm;
                }
                if ((lane&3)==0){ smr[rl*8+wn] = rm; smr[rl*8+4+wn] = rsum; }
            }
        __syncthreads();
        if (tid < 128){
            float m = -1e30f;
            #pragma unroll
            for (int w=0;w<4;w++) m = fmaxf(m, smr[tid*8+w]);
            float ssum = 0.f;
            #pragma unroll
            for (int w=0;w<4;w++) ssum += smr[tid*8+4+w]*__expf(smr[tid*8+w]-m);
            stats[((long long)z*1024 + m0 + tid)*16 + blockIdx.x] = make_float2(m, ssum);
        }
    } else {
        const int mrow = m0 + wm*32 + (lane>>2);
        const int ncol = n0 + wn*32 + (lane&3)*2;
        #pragma unroll
        for (int mi=0;mi<2;mi++)
            #pragma unroll
            for (int ni=0;ni<4;ni++)
                #pragma unroll
                for (int half=0; half<2; half++){
                    int r = mrow + mi*16 + half*8;
                    int c = ncol + ni*8;
                    float2 v;
                    v.x = acc[mi][ni][half*2+0]*alpha;
                    v.y = acc[mi][ni][half*2+1]*alpha;
                    *(float2*)(C + (long long)r*N + c) = v;
                }
    }
}

// ---------------- merge per-tile stats -> per-row (max, 1/l) ----------------
__global__ void merge_stats(const float2* __restrict__ stats,
                            float2* __restrict__ rs, int T)
{
    int r = blockIdx.x*256 + threadIdx.x;   // 16384 rows
    const float2* p = stats + (long long)r*16;
    float m = -1e30f;
    for (int t=0;t<T;t++) m = fmaxf(m, p[t].x);
    float l = 0.f;
    for (int t=0;t<T;t++) l += p[t].y*__expf(p[t].x - m);
    float inv = (m <= -1e29f || l <= 0.f) ? 0.f : 1.f/l;
    rs[r] = make_float2(m, inv);
}

// ---------------- transpose: out[z][c][r] = in[z][r][c] ----------------
__global__ void transpose_k(const float* __restrict__ in, float* __restrict__ out,
                            int R, int C, long long sIn, long long sOut)
{
    __shared__ float t[32][33];
    const int z = blockIdx.z;
    in += (long long)z*sIn; out += (long long)z*sOut;
    int r0 = blockIdx.y*32, c0 = blockIdx.x*32;
    #pragma unroll
    for (int j=0;j<4;j++)
        t[threadIdx.y+j*8][threadIdx.x] = in[(long long)(r0+threadIdx.y+j*8)*C + c0+threadIdx.x];
    __syncthreads();
    #pragma unroll
    for (int j=0;j<4;j++)
        out[(long long)(c0+threadIdx.y+j*8)*R + r0+threadIdx.x] = t[threadIdx.x][threadIdx.y+j*8];
}

// ---------------- mask dtype detection (0=int32,1=uint8,2=float32) ----------
__global__ void detect_mask_kernel(const uint32_t* __restrict__ m, int nw, int* __restrict__ f)
{
    __shared__ int wg, bb;
    if (threadIdx.x==0){ wg=0; bb=0; }
    __syncthreads();
    int lw=0, lb=0;
    for (int i=threadIdx.x;i<nw;i+=blockDim.x){
        uint32_t w = m[i];
        if (w>1u) lw=1;
        #pragma unroll
        for (int b=0;b<4;b++) if (((w>>(8*b))&0xFFu)>1u) lb=1;
    }
    if (lw) atomicOr(&wg,1);
    if (lb) atomicOr(&bb,1);
    __syncthreads();
    if (threadIdx.x==0) *f = (!wg)?0:((!bb)?1:2);
}

// ---------------- LN + residual / final add ----------------
__device__ __forceinline__ float blk_red(float v){
    __shared__ float sh[256];
    int t = threadIdx.x; sh[t]=v; __syncthreads();
    #pragma unroll
    for (int s=128;s>0;s>>=1){ if (t<s) sh[t]=sh[t]+sh[t+s]; __syncthreads(); }
    float r = sh[0]; __syncthreads(); return r;
}

__global__ __launch_bounds__(256)
void ln_res_kernel(const float* __restrict__ x, const float* __restrict__ res,
                   const float* __restrict__ gm, const float* __restrict__ bt,
                   float* __restrict__ out)
{
    const long long row = blockIdx.x;
    const int t = threadIdx.x;
    float v = x[row*HDIM+t];
    float mu = blk_red(v)*(1.f/HDIM);
    float d = v-mu;
    float var = blk_red(d*d)*(1.f/HDIM);
    out[row*HDIM+t] = d*rsqrtf(var+1e-5f)*gm[t]+bt[t] + res[row*HDIM+t];
}

__global__ void add_kernel(const float* __restrict__ a, const float* __restrict__ b,
                           float* __restrict__ o, long long n)
{
    long long i = (long long)blockIdx.x*blockDim.x + threadIdx.x;
    if (i<n) o[i] = a[i]+b[i];
}

// ---------------- host orchestration ----------------
static void run_layer(const float* x1, const float* x2, const void* mask,
                      const int* mt, int Nk,
                      const float* wqT, const float* bq_l,
                      const float* wkT, const float* bk_l,
                      const float* wvT, const float* bv_l,
                      const float* gm, const float* bt, float* xout,
                      float* q, float* k, float* v, float* vt, float* s,
                      float* at, float2* stats, float2* rsb)
{
    const int Bb=16, Nq=1024;
    proj_fused<<<Bb*Nq/128, 512, PSMEM>>>(x1, wqT, bq_l, q);
    proj_fused<<<Bb*Nk/128, 512, PSMEM>>>(x2, wkT, bk_l, k);
    proj_fused<<<Bb*Nk/128, 512, PSMEM>>>(x2, wvT, bv_l, v);
    {
        dim3 g(HDIM/32, Nk/32, Bb);
        transpose_k<<<g, dim3(32,8)>>>(v, vt, Nk, HDIM, (long long)Nk*HDIM, (long long)Nk*HDIM);
    }
    // QK: masked scaled scores + softmax partials
    {
        dim3 g(Nk/128, Nq/128, Bb);
        gemm_attn<0><<<g, 512, GSMEM>>>(q, k, s, Nk, HDIM,
            (long long)Nq*HDIM, (long long)Nk*HDIM, (long long)Nq*Nk, 0.0625f,
            mask, mt, stats, nullptr);
    }
    merge_stats<<<64, 256>>>(stats, rsb, Nk/128);
    // SV: softmax applied on A load
    {
        dim3 g(HDIM/128, Nq/128, Bb);
        gemm_attn<1><<<g, 512, GSMEM>>>(s, vt, at, HDIM, Nk,
            (long long)Nq*Nk, (long long)Nk*HDIM, (long long)Nq*HDIM, 1.f,
            nullptr, nullptr, nullptr, rsb);
    }
    ln_res_kernel<<<Bb*Nq, 256>>>(at, x1, gm, bt, xout);
}

extern "C" void kernel_launch(void* const* d_in, const int* in_sizes, int n_in,
                              void* d_out, int out_size)
{
    const float* future  = (const float*)d_in[0];
    const float* history = (const float*)d_in[1];
    const float* graph   = (const float*)d_in[2];
    const void*  mask_hf = d_in[3];
    const void*  mask_fg = d_in[4];
    const float* Wq = (const float*)d_in[5];
    const float* bq = (const float*)d_in[6];
    const float* Wk = (const float*)d_in[7];
    const float* bk = (const float*)d_in[8];
    const float* Wv = (const float*)d_in[9];
    const float* bv = (const float*)d_in[10];
    const float* gm = (const float*)d_in[11];
    const float* bt = (const float*)d_in[12];
    float* out = (float*)d_out;

    cudaFuncSetAttribute(gemm_attn<0>, cudaFuncAttributeMaxDynamicSharedMemorySize, GSMEM);
    cudaFuncSetAttribute(gemm_attn<1>, cudaFuncAttributeMaxDynamicSharedMemorySize, GSMEM);
    cudaFuncSetAttribute(proj_fused,   cudaFuncAttributeMaxDynamicSharedMemorySize, PSMEM);

    float *q,*k,*v,*vt,*s,*at,*xA,*xB,*wqT,*wkT,*wvT;
    float2 *stats,*rsb;
    int *mhf,*mfg;
    cudaGetSymbolAddress((void**)&q,g_q);     cudaGetSymbolAddress((void**)&k,g_k);
    cudaGetSymbolAddress((void**)&v,g_v);     cudaGetSymbolAddress((void**)&vt,g_vt);
    cudaGetSymbolAddress((void**)&s,g_s);     cudaGetSymbolAddress((void**)&at,g_at);
    cudaGetSymbolAddress((void**)&xA,g_xA);   cudaGetSymbolAddress((void**)&xB,g_xB);
    cudaGetSymbolAddress((void**)&wqT,g_wqT); cudaGetSymbolAddress((void**)&wkT,g_wkT);
    cudaGetSymbolAddress((void**)&wvT,g_wvT);
    cudaGetSymbolAddress((void**)&stats,g_stats);
    cudaGetSymbolAddress((void**)&rsb,g_rs);
    cudaGetSymbolAddress((void**)&mhf,g_mt_hf); cudaGetSymbolAddress((void**)&mfg,g_mt_fg);

    {
        int nh = in_sizes[3]/4; if (nh>65536) nh=65536;
        int ng = in_sizes[4]/4; if (ng>65536) ng=65536;
        detect_mask_kernel<<<1,256>>>((const uint32_t*)mask_hf, nh, mhf);
        detect_mask_kernel<<<1,256>>>((const uint32_t*)mask_fg, ng, mfg);
    }
    {
        dim3 g(8,8,12), b(32,8);
        transpose_k<<<g,b>>>(Wq, wqT, 256,256, 65536,65536);
        transpose_k<<<g,b>>>(Wk, wkT, 256,256, 65536,65536);
        transpose_k<<<g,b>>>(Wv, wvT, 256,256, 65536,65536);
    }

    const long long WL = 3LL*65536, BL = 3LL*256;
    run_layer(future, history, mask_hf, mhf, 1024,
              wqT+0*WL, bq+0*BL, wkT+0*WL, bk+0*BL, wvT+0*WL, bv+0*BL,
              gm+0*256, bt+0*256, xA, q,k,v,vt,s,at,stats,rsb);
    run_layer(xA, history, mask_hf, mhf, 1024,
              wqT+1*WL, bq+1*BL, wkT+1*WL, bk+1*BL, wvT+1*WL, bv+1*BL,
              gm+1*256, bt+1*256, xB, q,k,v,vt,s,at,stats,rsb);
    run_layer(xB, graph, mask_fg, mfg, 2048,
              wqT+2*WL, bq+2*BL, wkT+2*WL, bk+2*BL, wvT+2*WL, bv+2*BL,
              gm+2*256, bt+2*256, xA, q,k,v,vt,s,at,stats,rsb);
    run_layer(xA, graph, mask_fg, mfg, 2048,
              wqT+3*WL, bq+3*BL, wkT+3*WL, bk+3*BL, wvT+3*WL, bv+3*BL,
              gm+3*256, bt+3*256, xB, q,k,v,vt,s,at,stats,rsb);

    long long n = (long long)out_size;
    add_kernel<<<(unsigned)((n+255)/256),256>>>(future, xB, out, n);
}